// round 14
// baseline (speedup 1.0000x reference)
#include <cuda_runtime.h>
#include <cuda_bf16.h>
#include <cstdint>

#define HH 8
#define DD 512
#define BB 128
#define SS 2048
#define EE 4096   // HH*DD
#define KSPLIT 4

// Scratch (no allocations allowed)
__device__ float g_q[BB * EE];             // projected, pre-scaled query
__device__ float g_x[BB * EE];             // attention output
__device__ float g_part[KSPLIT * BB * EE]; // k-split GEMM partials

// Single dynamic-smem symbol for the whole TU
extern __shared__ char dyn_smem[];

__device__ __forceinline__ void fma4(float4& a, float p, float4 v) {
    a.x += p * v.x; a.y += p * v.y; a.z += p * v.z; a.w += p * v.w;
}

// m16n8k16 row.col bf16 mma, fp32 accumulate (standard PTX, sm_80+)
__device__ __forceinline__ void mma16816(float* c, const uint32_t* a, const uint32_t* b) {
    asm volatile(
        "mma.sync.aligned.m16n8k16.row.col.f32.bf16.bf16.f32 "
        "{%0,%1,%2,%3}, {%4,%5,%6,%7}, {%8,%9}, {%0,%1,%2,%3};"
        : "+f"(c[0]), "+f"(c[1]), "+f"(c[2]), "+f"(c[3])
        : "r"(a[0]), "r"(a[1]), "r"(a[2]), "r"(a[3]), "r"(b[0]), "r"(b[1]));
}

// pack float2 -> bf16x2 (hi) and residual (lo)
__device__ __forceinline__ uint32_t bfhi(float2 v) {
    __nv_bfloat162 h = __floats2bfloat162_rn(v.x, v.y);
    return *(uint32_t*)&h;
}
__device__ __forceinline__ uint32_t bflo(float2 v, uint32_t hbits) {
    __nv_bfloat162 h = *(__nv_bfloat162*)&hbits;
    float2 f = __bfloat1622float2(h);
    __nv_bfloat162 l = __floats2bfloat162_rn(v.x - f.x, v.y - f.y);
    return *(uint32_t*)&l;
}

__device__ __forceinline__ uint32_t smem_u32(const void* p) {
    uint32_t a;
    asm("{ .reg .u64 t; cvta.to.shared.u64 t, %1; cvt.u32.u64 %0, t; }"
        : "=r"(a) : "l"(p));
    return a;
}
__device__ __forceinline__ void cp16(uint32_t s, const void* g) {
    asm volatile("cp.async.cg.shared.global [%0], [%1], 16;" :: "r"(s), "l"(g));
}
#define CP_COMMIT() asm volatile("cp.async.commit_group;" ::: "memory")
#define CP_WAIT1()  asm volatile("cp.async.wait_group 1;" ::: "memory")

// ===========================================================================
// gemm_part<K, KCHUNK>: part[p] = X[128,K_range] @ W[4096,K_range]^T
// BM=128, BN=64 -> grid (64, KSPLIT) = 256 CTAs, 2 CTAs/SM.
// R11 dataflow + software-pipelined A-fragment LDS in the compute loop.
// ===========================================================================
#define KSTEP 32
#define ASTRIDE 132               // words per A slot (128 data + 4 skew)
#define BSTRIDE 66                // words per B slot (64 data + 2 skew)
#define A_REG (16 * ASTRIDE)      // 2112 words per Ah/Al
#define B_REG (16 * BSTRIDE)      // 1056 words per Bh/Bl
#define BUFW2 (2 * A_REG + 2 * B_REG)  // 6336 words per frag buffer
#define RAWSTAGE 6144             // floats: A 4096 + B 2048
#define GEMM_SMEM (2 * BUFW2 * 4 + 2 * RAWSTAGE * 4)  // 50688 + 49152 = 99840

template <int K, int KCHUNK>
__global__ void __launch_bounds__(256, 2)
gemm_part(const float* __restrict__ X, const float* __restrict__ W,
          float* __restrict__ part) {
    uint32_t* sw = (uint32_t*)dyn_smem;                    // frag buffers
    float* raw = (float*)(dyn_smem + 2 * BUFW2 * 4);       // raw stages
    const uint32_t raw_u = smem_u32(raw);
    const int tid = threadIdx.x;
    const int wid = tid >> 5;
    const int lane = tid & 31;
    const int wm = wid >> 2;          // 0..1: M half (64 rows)
    const int wn = wid & 3;           // 0..3: N quarter (16 cols)
    const int g = lane >> 2;
    const int tg = lane & 3;
    const int fbase = blockIdx.x * 64;
    const int p = blockIdx.y;
    const int kbeg = p * KCHUNK;

    float acc[4][2][4];
    #pragma unroll
    for (int mi = 0; mi < 4; mi++)
        #pragma unroll
        for (int ni = 0; ni < 2; ni++)
            #pragma unroll
            for (int r = 0; r < 4; r++) acc[mi][ni][r] = 0.0f;

    const int NC = KCHUNK / KSTEP;

    auto issue = [&](int c, int s) {
        const int k0 = kbeg + c * KSTEP;
        const uint32_t base = raw_u + s * RAWSTAGE * 4;
        #pragma unroll
        for (int i = 0; i < 4; i++) {
            const int idx = tid + i * 256;
            const int row = idx >> 3, q4 = idx & 7;
            cp16(base + (row * 32 + q4 * 4) * 4, X + (size_t)row * K + k0 + q4 * 4);
        }
        #pragma unroll
        for (int i = 0; i < 2; i++) {
            const int idx = tid + i * 256;
            const int row = idx >> 3, q4 = idx & 7;
            cp16(base + (4096 + row * 32 + q4 * 4) * 4,
                 W + (size_t)(fbase + row) * K + k0 + q4 * 4);
        }
    };

    auto convert = [&](int c) {
        const int q = c & 1;
        const float* rA = raw + q * RAWSTAGE;
        const float* rB = rA + 4096;
        uint32_t* Ah = sw + q * BUFW2;
        uint32_t* Al = Ah + A_REG;
        uint32_t* Bh = Al + A_REG;
        uint32_t* Bl = Bh + B_REG;
        #pragma unroll
        for (int i = 0; i < 4; i++) {
            const int idx = tid + i * 256;
            const int row = idx >> 3, q4 = idx & 7;
            float4 v = *(const float4*)(rA + row * 32 + q4 * 4);
            uint32_t h01 = bfhi(make_float2(v.x, v.y));
            uint32_t h23 = bfhi(make_float2(v.z, v.w));
            uint32_t l01 = bflo(make_float2(v.x, v.y), h01);
            uint32_t l23 = bflo(make_float2(v.z, v.w), h23);
            const int gr = row & 7, rhalf = (row >> 3) & 1;
            const int sA = (((row >> 6) * 4 + ((row >> 4) & 3)) * 2) + (q4 >> 2);
            const int j = rhalf + 2 * ((q4 >> 1) & 1);
            const int ln0 = gr * 4 + 2 * (q4 & 1);
            const int o0 = sA * ASTRIDE + ln0 * 4 + j;
            Ah[o0]     = h01;
            Ah[o0 + 4] = h23;
            Al[o0]     = l01;
            Al[o0 + 4] = l23;
        }
        #pragma unroll
        for (int i = 0; i < 2; i++) {
            const int idx = tid + i * 256;
            const int row = idx >> 3, q4 = idx & 7;
            float4 v = *(const float4*)(rB + row * 32 + q4 * 4);
            uint32_t h01 = bfhi(make_float2(v.x, v.y));
            uint32_t h23 = bfhi(make_float2(v.z, v.w));
            uint32_t l01 = bflo(make_float2(v.x, v.y), h01);
            uint32_t l23 = bflo(make_float2(v.z, v.w), h23);
            const int gr = row & 7;
            const int sB = (((row >> 4) * 2 + ((row >> 3) & 1)) * 2) + (q4 >> 2);
            const int j = (q4 >> 1) & 1;
            const int ln0 = gr * 4 + 2 * (q4 & 1);
            const int o0 = sB * BSTRIDE + ln0 * 2 + j;
            Bh[o0]     = h01;
            Bh[o0 + 2] = h23;
            Bl[o0]     = l01;
            Bl[o0 + 2] = l23;
        }
    };

    issue(0, 0); CP_COMMIT();
    issue(1, 1); CP_COMMIT();
    CP_WAIT1();
    convert(0);
    __syncthreads();

    for (int c = 0; c < NC; c++) {
        const int q = c & 1;
        if (c + 2 < NC) issue(c + 2, q);
        CP_COMMIT();

        uint32_t* Ah = sw + q * BUFW2;
        uint32_t* Al = Ah + A_REG;
        uint32_t* Bh = Al + A_REG;
        uint32_t* Bl = Bh + B_REG;
        #pragma unroll
        for (int sub = 0; sub < 2; sub++) {
            uint2 bh[2], bl[2];
            #pragma unroll
            for (int ni = 0; ni < 2; ni++) {
                const int sB = (wn * 2 + ni) * 2 + sub;
                bh[ni] = *(const uint2*)(Bh + sB * BSTRIDE + lane * 2);
                bl[ni] = *(const uint2*)(Bl + sB * BSTRIDE + lane * 2);
            }
            // software-pipelined A frags: load mi+1 while mma on mi
            uint4 ahv = *(const uint4*)(Ah + ((wm * 4) * 2 + sub) * ASTRIDE + lane * 4);
            uint4 alv = *(const uint4*)(Al + ((wm * 4) * 2 + sub) * ASTRIDE + lane * 4);
            #pragma unroll
            for (int mi = 0; mi < 4; mi++) {
                uint4 ahn, aln;
                if (mi < 3) {
                    const int sA = (wm * 4 + mi + 1) * 2 + sub;
                    ahn = *(const uint4*)(Ah + sA * ASTRIDE + lane * 4);
                    aln = *(const uint4*)(Al + sA * ASTRIDE + lane * 4);
                }
                #pragma unroll
                for (int ni = 0; ni < 2; ni++) {
                    mma16816(acc[mi][ni], (const uint32_t*)&ahv, (const uint32_t*)&bh[ni]);
                    mma16816(acc[mi][ni], (const uint32_t*)&alv, (const uint32_t*)&bh[ni]);
                    mma16816(acc[mi][ni], (const uint32_t*)&ahv, (const uint32_t*)&bl[ni]);
                }
                if (mi < 3) { ahv = ahn; alv = aln; }
            }
        }

        CP_WAIT1();
        if (c + 1 < NC) convert(c + 1);
        __syncthreads();
    }

    float* pp = part + (size_t)p * BB * EE;
    #pragma unroll
    for (int mi = 0; mi < 4; mi++) {
        const int m0 = wm * 64 + mi * 16 + g;
        #pragma unroll
        for (int ni = 0; ni < 2; ni++) {
            const int col = fbase + wn * 16 + ni * 8 + tg * 2;
            *(float2*)(pp + (size_t)m0 * EE + col)       = make_float2(acc[mi][ni][0], acc[mi][ni][1]);
            *(float2*)(pp + (size_t)(m0 + 8) * EE + col) = make_float2(acc[mi][ni][2], acc[mi][ni][3]);
        }
    }
}

// out = (sum_p part[p] + bias) * scale
__global__ void __launch_bounds__(256) reduce_part(const float* __restrict__ bias,
                                                   float* __restrict__ out, float scale) {
    const int t = blockIdx.x * 256 + threadIdx.x;
    const int base = t * 4;
    const int col = base & (EE - 1);
    float4 a = *(const float4*)(g_part + base);
    float4 b = *(const float4*)(g_part + 1 * BB * EE + base);
    float4 c = *(const float4*)(g_part + 2 * BB * EE + base);
    float4 d = *(const float4*)(g_part + 3 * BB * EE + base);
    float4 bi = *(const float4*)(bias + col);
    float4 o;
    o.x = (a.x + b.x + c.x + d.x + bi.x) * scale;
    o.y = (a.y + b.y + c.y + d.y + bi.y) * scale;
    o.z = (a.z + b.z + c.z + d.z + bi.z) * scale;
    o.w = (a.w + b.w + c.w + d.w + bi.w) * scale;
    *(float4*)(out + base) = o;
}

// ---------------------------------------------------------------------------
// Kernel B: fused attention. One CTA (1024 threads, 32 warps) per batch b.
// pass1: 3 independent mma accumulator chains (hh, lh, hl), summed at end.
// ---------------------------------------------------------------------------
__global__ void __launch_bounds__(1024, 1) attn_kernel(const float* __restrict__ key,
                                                       const float* __restrict__ value,
                                                       const int* __restrict__ mask) {
    float* sc = (float*)dyn_smem;                       // 16384 floats
    uint2* qbA = (uint2*)(dyn_smem + 65536);            // [32 ks][32 lane]
    uint2* qbB = (uint2*)(dyn_smem + 65536 + 8192);
    __shared__ float red[HH][33];
    __shared__ float fin[HH];

    const int b = blockIdx.x;
    const int tid = threadIdx.x;
    const int warp = tid >> 5;
    const int lane = tid & 31;
    const int gid = lane >> 2;
    const int tg = lane & 3;

    // build q B-frag tables (hi/lo)
    {
        const int ks = tid >> 5, L = tid & 31;
        const int h = L >> 2, d0 = ks * 16 + (L & 3) * 2;
        const float* qp = g_q + (size_t)b * EE + h * DD + d0;
        float2 v0 = make_float2(qp[0], qp[1]);
        float2 v1 = make_float2(qp[8], qp[9]);
        uint32_t h0 = bfhi(v0), l0 = bflo(v0, h0);
        uint32_t h1 = bfhi(v1), l1 = bflo(v1, h1);
        qbA[tid] = make_uint2(h0, h1);
        qbB[tid] = make_uint2(l0, l1);
    }
    __syncthreads();

    // ---- scores via mma: warp handles 4 m-tiles of 16 s ----
    const float* Kb = key + (size_t)b * SS * DD;
    const int*   Mb = mask + (size_t)b * SS;

    for (int i = 0; i < 4; i++) {
        const int mt = warp * 4 + i;
        const int s0 = mt * 16 + gid;
        const float* K0 = Kb + (size_t)s0 * DD + tg * 2;
        float chh[4] = {0, 0, 0, 0}, clh[4] = {0, 0, 0, 0}, chl[4] = {0, 0, 0, 0};
        #pragma unroll 4
        for (int ks = 0; ks < 32; ks++) {
            const float* kp = K0 + ks * 16;
            float2 va0 = *(const float2*)(kp);
            float2 va1 = *(const float2*)(kp + 8 * DD);
            float2 va2 = *(const float2*)(kp + 8);
            float2 va3 = *(const float2*)(kp + 8 * DD + 8);
            uint32_t ah[4], al[4];
            ah[0] = bfhi(va0); al[0] = bflo(va0, ah[0]);
            ah[1] = bfhi(va1); al[1] = bflo(va1, ah[1]);
            ah[2] = bfhi(va2); al[2] = bflo(va2, ah[2]);
            ah[3] = bfhi(va3); al[3] = bflo(va3, ah[3]);
            uint2 bh = qbA[ks * 32 + lane];
            uint2 bl = qbB[ks * 32 + lane];
            mma16816(chh, ah, (const uint32_t*)&bh);
            mma16816(clh, al, (const uint32_t*)&bh);
            mma16816(chl, ah, (const uint32_t*)&bl);
        }
        float c[4];
        #pragma unroll
        for (int r = 0; r < 4; r++) c[r] = chh[r] + clh[r] + chl[r];
        const int s1 = s0 + 8, h0 = tg * 2;
        const int m0 = Mb[s0], m1 = Mb[s1];
        sc[s0 * 8 + h0]     = m0 ? c[0] : -1e9f;
        sc[s0 * 8 + h0 + 1] = m0 ? c[1] : -1e9f;
        sc[s1 * 8 + h0]     = m1 ? c[2] : -1e9f;
        sc[s1 * 8 + h0 + 1] = m1 ? c[3] : -1e9f;
    }
    __syncthreads();

    // ---- softmax: thread owns 2 contiguous s-rows (16 floats) ----
    {
        const int base = tid * 16;
        float4 r[4];
        #pragma unroll
        for (int i = 0; i < 4; i++) r[i] = *(float4*)(sc + base + i * 4);

        float m[HH];
        m[0] = fmaxf(r[0].x, r[2].x); m[1] = fmaxf(r[0].y, r[2].y);
        m[2] = fmaxf(r[0].z, r[2].z); m[3] = fmaxf(r[0].w, r[2].w);
        m[4] = fmaxf(r[1].x, r[3].x); m[5] = fmaxf(r[1].y, r[3].y);
        m[6] = fmaxf(r[1].z, r[3].z); m[7] = fmaxf(r[1].w, r[3].w);
        #pragma unroll
        for (int off = 16; off; off >>= 1)
            #pragma unroll
            for (int h = 0; h < HH; h++)
                m[h] = fmaxf(m[h], __shfl_xor_sync(0xffffffffu, m[h], off));
        if (lane < HH) red[lane][warp] = m[lane];
        __syncthreads();
        if (warp < HH) {
            float v = red[warp][lane];
            #pragma unroll
            for (int off = 16; off; off >>= 1)
                v = fmaxf(v, __shfl_xor_sync(0xffffffffu, v, off));
            if (lane == 0) fin[warp] = v;
        }
        __syncthreads();
        #pragma unroll
        for (int h = 0; h < HH; h++) m[h] = fin[h];
        __syncthreads();

        float s[HH];
        #pragma unroll
        for (int h = 0; h < HH; h++) s[h] = 0.0f;
        #pragma unroll
        for (int i = 0; i < 4; i++) {
            const int hb = (i & 1) * 4;
            r[i].x = __expf(r[i].x - m[hb + 0]); s[hb + 0] += r[i].x;
            r[i].y = __expf(r[i].y - m[hb + 1]); s[hb + 1] += r[i].y;
            r[i].z = __expf(r[i].z - m[hb + 2]); s[hb + 2] += r[i].z;
            r[i].w = __expf(r[i].w - m[hb + 3]); s[hb + 3] += r[i].w;
        }
        #pragma unroll
        for (int off = 16; off; off >>= 1)
            #pragma unroll
            for (int h = 0; h < HH; h++)
                s[h] += __shfl_xor_sync(0xffffffffu, s[h], off);
        if (lane < HH) red[lane][warp] = s[lane];
        __syncthreads();
        if (warp < HH) {
            float v = red[warp][lane];
            #pragma unroll
            for (int off = 16; off; off >>= 1)
                v += __shfl_xor_sync(0xffffffffu, v, off);
            if (lane == 0) fin[warp] = 1.0f / v;
        }
        __syncthreads();
        #pragma unroll
        for (int h = 0; h < HH; h++) s[h] = fin[h];

        #pragma unroll
        for (int i = 0; i < 4; i++) {
            const int hb = (i & 1) * 4;
            r[i].x *= s[hb + 0];
            r[i].y *= s[hb + 1];
            r[i].z *= s[hb + 2];
            r[i].w *= s[hb + 3];
            *(float4*)(sc + base + i * 4) = r[i];
        }
    }
    __syncthreads();

    // ---- pass 2: thread owns (d-quad, head-quad, s-quarter) ----
    const int d4 = (tid & 127) * 4;
    const int h0 = ((tid >> 7) & 1) * 4;
    const int sg = tid >> 8;             // 0..3
    const float* Vb = value + (size_t)b * SS * DD;

    float4 a0 = {0,0,0,0}, a1 = a0, a2 = a0, a3 = a0;
    const int s_beg = sg * 512;
    #pragma unroll 2
    for (int s = s_beg; s < s_beg + 512; s += 2) {
        float4 v0 = *(const float4*)(Vb + (size_t)s * DD + d4);
        float4 v1 = *(const float4*)(Vb + (size_t)(s + 1) * DD + d4);
        float4 p0 = *(const float4*)(sc + s * 8 + h0);
        float4 p1 = *(const float4*)(sc + (s + 1) * 8 + h0);
        fma4(a0, p0.x, v0); fma4(a1, p0.y, v0); fma4(a2, p0.z, v0); fma4(a3, p0.w, v0);
        fma4(a0, p1.x, v1); fma4(a1, p1.y, v1); fma4(a2, p1.z, v1); fma4(a3, p1.w, v1);
    }
    __syncthreads();  // everyone done reading sc (reuse as 4 partial buffers)

    {
        float* dst = sc + sg * 4096;
        *(float4*)(dst + (h0 + 0) * DD + d4) = a0;
        *(float4*)(dst + (h0 + 1) * DD + d4) = a1;
        *(float4*)(dst + (h0 + 2) * DD + d4) = a2;
        *(float4*)(dst + (h0 + 3) * DD + d4) = a3;
    }
    __syncthreads();

    const int idx = tid * 4;
    float4 r0 = *(float4*)(sc + idx);
    float4 r1 = *(float4*)(sc + 4096 + idx);
    float4 r2 = *(float4*)(sc + 8192 + idx);
    float4 r3 = *(float4*)(sc + 12288 + idx);
    float4 r;
    r.x = r0.x + r1.x + r2.x + r3.x;
    r.y = r0.y + r1.y + r2.y + r3.y;
    r.z = r0.z + r1.z + r2.z + r3.z;
    r.w = r0.w + r1.w + r2.w + r3.w;
    *(float4*)(g_x + (size_t)b * EE + idx) = r;
}

// ---------------------------------------------------------------------------
extern "C" void kernel_launch(void* const* d_in, const int* in_sizes, int n_in,
                              void* d_out, int out_size) {
    const float* query = (const float*)d_in[0];
    const float* key   = (const float*)d_in[1];
    const float* value = (const float*)d_in[2];
    const int*   mask  = (const int*)d_in[3];
    const float* W_in  = (const float*)d_in[4];
    const float* b_in  = (const float*)d_in[5];
    const float* W_out = (const float*)d_in[6];
    const float* b_out = (const float*)d_in[7];
    float* out = (float*)d_out;

    const int smem_attn = 81920;  // sc 64K + qbA 8K + qbB 8K
    cudaFuncSetAttribute(attn_kernel, cudaFuncAttributeMaxDynamicSharedMemorySize, smem_attn);
    cudaFuncSetAttribute(gemm_part<512, 128>,   cudaFuncAttributeMaxDynamicSharedMemorySize, GEMM_SMEM);
    cudaFuncSetAttribute(gemm_part<4096, 1024>, cudaFuncAttributeMaxDynamicSharedMemorySize, GEMM_SMEM);

    float* gq; cudaGetSymbolAddress((void**)&gq, g_q);
    float* gx; cudaGetSymbolAddress((void**)&gx, g_x);
    float* gp; cudaGetSymbolAddress((void**)&gp, g_part);

    dim3 ggrid(EE / 64, KSPLIT);   // 256 CTAs

    gemm_part<512, 128><<<ggrid, 256, GEMM_SMEM>>>(query, W_in, gp);
    reduce_part<<<BB * EE / 1024, 256>>>(b_in, gq, 0.04419417382415922f);
    attn_kernel<<<BB, 1024, smem_attn>>>(key, value, mask);
    gemm_part<4096, 1024><<<ggrid, 256, GEMM_SMEM>>>(gx, W_out, gp);
    reduce_part<<<BB * EE / 1024, 256>>>(b_out, out, 1.0f);
}

// round 15
// speedup vs baseline: 1.0564x; 1.0564x over previous
#include <cuda_runtime.h>
#include <cuda_bf16.h>
#include <cstdint>

#define HH 8
#define DD 512
#define BB 128
#define SS 2048
#define EE 4096   // HH*DD
#define KSPLIT 4
#define QSCALE 0.04419417382415922f

// Scratch (no allocations allowed)
__device__ float g_x[BB * EE];             // attention output
__device__ float g_part[KSPLIT * BB * EE]; // k-split GEMM partials

// Single dynamic-smem symbol for the whole TU
extern __shared__ char dyn_smem[];

__device__ __forceinline__ void fma4(float4& a, float p, float4 v) {
    a.x += p * v.x; a.y += p * v.y; a.z += p * v.z; a.w += p * v.w;
}

// m16n8k16 row.col bf16 mma, fp32 accumulate (standard PTX, sm_80+)
__device__ __forceinline__ void mma16816(float* c, const uint32_t* a, const uint32_t* b) {
    asm volatile(
        "mma.sync.aligned.m16n8k16.row.col.f32.bf16.bf16.f32 "
        "{%0,%1,%2,%3}, {%4,%5,%6,%7}, {%8,%9}, {%0,%1,%2,%3};"
        : "+f"(c[0]), "+f"(c[1]), "+f"(c[2]), "+f"(c[3])
        : "r"(a[0]), "r"(a[1]), "r"(a[2]), "r"(a[3]), "r"(b[0]), "r"(b[1]));
}

// pack float2 -> bf16x2 (hi) and residual (lo)
__device__ __forceinline__ uint32_t bfhi(float2 v) {
    __nv_bfloat162 h = __floats2bfloat162_rn(v.x, v.y);
    return *(uint32_t*)&h;
}
__device__ __forceinline__ uint32_t bflo(float2 v, uint32_t hbits) {
    __nv_bfloat162 h = *(__nv_bfloat162*)&hbits;
    float2 f = __bfloat1622float2(h);
    __nv_bfloat162 l = __floats2bfloat162_rn(v.x - f.x, v.y - f.y);
    return *(uint32_t*)&l;
}

__device__ __forceinline__ uint32_t smem_u32(const void* p) {
    uint32_t a;
    asm("{ .reg .u64 t; cvta.to.shared.u64 t, %1; cvt.u32.u64 %0, t; }"
        : "=r"(a) : "l"(p));
    return a;
}
__device__ __forceinline__ void cp16(uint32_t s, const void* g) {
    asm volatile("cp.async.cg.shared.global [%0], [%1], 16;" :: "r"(s), "l"(g));
}
#define CP_COMMIT() asm volatile("cp.async.commit_group;" ::: "memory")
#define CP_WAIT1()  asm volatile("cp.async.wait_group 1;" ::: "memory")

// ===========================================================================
// gemm_part<K, KCHUNK>: part[p] = X[128,K_range] @ W[4096,K_range]^T
// BM=128, BN=64 -> grid (64, KSPLIT) = 256 CTAs, 2 CTAs/SM.  (R11 body)
// ===========================================================================
#define KSTEP 32
#define ASTRIDE 132               // words per A slot (128 data + 4 skew)
#define BSTRIDE 66                // words per B slot (64 data + 2 skew)
#define A_REG (16 * ASTRIDE)      // 2112 words per Ah/Al
#define B_REG (16 * BSTRIDE)      // 1056 words per Bh/Bl
#define BUFW2 (2 * A_REG + 2 * B_REG)  // 6336 words per frag buffer
#define RAWSTAGE 6144             // floats: A 4096 + B 2048
#define GEMM_SMEM (2 * BUFW2 * 4 + 2 * RAWSTAGE * 4)  // 50688 + 49152 = 99840

template <int K, int KCHUNK>
__global__ void __launch_bounds__(256, 2)
gemm_part(const float* __restrict__ X, const float* __restrict__ W,
          float* __restrict__ part) {
    uint32_t* sw = (uint32_t*)dyn_smem;                    // frag buffers
    float* raw = (float*)(dyn_smem + 2 * BUFW2 * 4);       // raw stages
    const uint32_t raw_u = smem_u32(raw);
    const int tid = threadIdx.x;
    const int wid = tid >> 5;
    const int lane = tid & 31;
    const int wm = wid >> 2;          // 0..1: M half (64 rows)
    const int wn = wid & 3;           // 0..3: N quarter (16 cols)
    const int g = lane >> 2;
    const int tg = lane & 3;
    const int fbase = blockIdx.x * 64;
    const int p = blockIdx.y;
    const int kbeg = p * KCHUNK;

    float acc[4][2][4];
    #pragma unroll
    for (int mi = 0; mi < 4; mi++)
        #pragma unroll
        for (int ni = 0; ni < 2; ni++)
            #pragma unroll
            for (int r = 0; r < 4; r++) acc[mi][ni][r] = 0.0f;

    const int NC = KCHUNK / KSTEP;

    auto issue = [&](int c, int s) {
        const int k0 = kbeg + c * KSTEP;
        const uint32_t base = raw_u + s * RAWSTAGE * 4;
        #pragma unroll
        for (int i = 0; i < 4; i++) {
            const int idx = tid + i * 256;
            const int row = idx >> 3, q4 = idx & 7;
            cp16(base + (row * 32 + q4 * 4) * 4, X + (size_t)row * K + k0 + q4 * 4);
        }
        #pragma unroll
        for (int i = 0; i < 2; i++) {
            const int idx = tid + i * 256;
            const int row = idx >> 3, q4 = idx & 7;
            cp16(base + (4096 + row * 32 + q4 * 4) * 4,
                 W + (size_t)(fbase + row) * K + k0 + q4 * 4);
        }
    };

    auto convert = [&](int c) {
        const int q = c & 1;
        const float* rA = raw + q * RAWSTAGE;
        const float* rB = rA + 4096;
        uint32_t* Ah = sw + q * BUFW2;
        uint32_t* Al = Ah + A_REG;
        uint32_t* Bh = Al + A_REG;
        uint32_t* Bl = Bh + B_REG;
        #pragma unroll
        for (int i = 0; i < 4; i++) {
            const int idx = tid + i * 256;
            const int row = idx >> 3, q4 = idx & 7;
            float4 v = *(const float4*)(rA + row * 32 + q4 * 4);
            uint32_t h01 = bfhi(make_float2(v.x, v.y));
            uint32_t h23 = bfhi(make_float2(v.z, v.w));
            uint32_t l01 = bflo(make_float2(v.x, v.y), h01);
            uint32_t l23 = bflo(make_float2(v.z, v.w), h23);
            const int gr = row & 7, rhalf = (row >> 3) & 1;
            const int sA = (((row >> 6) * 4 + ((row >> 4) & 3)) * 2) + (q4 >> 2);
            const int j = rhalf + 2 * ((q4 >> 1) & 1);
            const int ln0 = gr * 4 + 2 * (q4 & 1);
            const int o0 = sA * ASTRIDE + ln0 * 4 + j;
            Ah[o0]     = h01;
            Ah[o0 + 4] = h23;
            Al[o0]     = l01;
            Al[o0 + 4] = l23;
        }
        #pragma unroll
        for (int i = 0; i < 2; i++) {
            const int idx = tid + i * 256;
            const int row = idx >> 3, q4 = idx & 7;
            float4 v = *(const float4*)(rB + row * 32 + q4 * 4);
            uint32_t h01 = bfhi(make_float2(v.x, v.y));
            uint32_t h23 = bfhi(make_float2(v.z, v.w));
            uint32_t l01 = bflo(make_float2(v.x, v.y), h01);
            uint32_t l23 = bflo(make_float2(v.z, v.w), h23);
            const int gr = row & 7;
            const int sB = (((row >> 4) * 2 + ((row >> 3) & 1)) * 2) + (q4 >> 2);
            const int j = (q4 >> 1) & 1;
            const int ln0 = gr * 4 + 2 * (q4 & 1);
            const int o0 = sB * BSTRIDE + ln0 * 2 + j;
            Bh[o0]     = h01;
            Bh[o0 + 2] = h23;
            Bl[o0]     = l01;
            Bl[o0 + 2] = l23;
        }
    };

    issue(0, 0); CP_COMMIT();
    issue(1, 1); CP_COMMIT();
    CP_WAIT1();
    convert(0);
    __syncthreads();

    for (int c = 0; c < NC; c++) {
        const int q = c & 1;
        if (c + 2 < NC) issue(c + 2, q);
        CP_COMMIT();

        uint32_t* Ah = sw + q * BUFW2;
        uint32_t* Al = Ah + A_REG;
        uint32_t* Bh = Al + A_REG;
        uint32_t* Bl = Bh + B_REG;
        #pragma unroll
        for (int sub = 0; sub < 2; sub++) {
            uint2 bh[2], bl[2];
            #pragma unroll
            for (int ni = 0; ni < 2; ni++) {
                const int sB = (wn * 2 + ni) * 2 + sub;
                bh[ni] = *(const uint2*)(Bh + sB * BSTRIDE + lane * 2);
                bl[ni] = *(const uint2*)(Bl + sB * BSTRIDE + lane * 2);
            }
            #pragma unroll
            for (int mi = 0; mi < 4; mi++) {
                const int sA = (wm * 4 + mi) * 2 + sub;
                uint4 ahv = *(const uint4*)(Ah + sA * ASTRIDE + lane * 4);
                uint4 alv = *(const uint4*)(Al + sA * ASTRIDE + lane * 4);
                #pragma unroll
                for (int ni = 0; ni < 2; ni++) {
                    mma16816(acc[mi][ni], (const uint32_t*)&ahv, (const uint32_t*)&bh[ni]);
                    mma16816(acc[mi][ni], (const uint32_t*)&alv, (const uint32_t*)&bh[ni]);
                    mma16816(acc[mi][ni], (const uint32_t*)&ahv, (const uint32_t*)&bl[ni]);
                }
            }
        }

        CP_WAIT1();
        if (c + 1 < NC) convert(c + 1);
        __syncthreads();
    }

    float* pp = part + (size_t)p * BB * EE;
    #pragma unroll
    for (int mi = 0; mi < 4; mi++) {
        const int m0 = wm * 64 + mi * 16 + g;
        #pragma unroll
        for (int ni = 0; ni < 2; ni++) {
            const int col = fbase + wn * 16 + ni * 8 + tg * 2;
            *(float2*)(pp + (size_t)m0 * EE + col)       = make_float2(acc[mi][ni][0], acc[mi][ni][1]);
            *(float2*)(pp + (size_t)(m0 + 8) * EE + col) = make_float2(acc[mi][ni][2], acc[mi][ni][3]);
        }
    }
}

// out = (sum_p part[p] + bias) * scale
__global__ void __launch_bounds__(256) reduce_part(const float* __restrict__ bias,
                                                   float* __restrict__ out, float scale) {
    const int t = blockIdx.x * 256 + threadIdx.x;
    const int base = t * 4;
    const int col = base & (EE - 1);
    float4 a = *(const float4*)(g_part + base);
    float4 b = *(const float4*)(g_part + 1 * BB * EE + base);
    float4 c = *(const float4*)(g_part + 2 * BB * EE + base);
    float4 d = *(const float4*)(g_part + 3 * BB * EE + base);
    float4 bi = *(const float4*)(bias + col);
    float4 o;
    o.x = (a.x + b.x + c.x + d.x + bi.x) * scale;
    o.y = (a.y + b.y + c.y + d.y + bi.y) * scale;
    o.z = (a.z + b.z + c.z + d.z + bi.z) * scale;
    o.w = (a.w + b.w + c.w + d.w + bi.w) * scale;
    *(float4*)(out + base) = o;
}

// ---------------------------------------------------------------------------
// Kernel B: fused attention. One CTA (1024 threads, 32 warps) per batch b.
// q-table build folds the qproj k-split reduce: reads 4 g_part partials +
// bias, applies 1/sqrt(D) inline (same summation order as reduce_part).
// ---------------------------------------------------------------------------
__global__ void __launch_bounds__(1024, 1) attn_kernel(const float* __restrict__ key,
                                                       const float* __restrict__ value,
                                                       const int* __restrict__ mask,
                                                       const float* __restrict__ b_in) {
    float* sc = (float*)dyn_smem;                       // 16384 floats
    uint2* qbA = (uint2*)(dyn_smem + 65536);            // [32 ks][32 lane]
    uint2* qbB = (uint2*)(dyn_smem + 65536 + 8192);
    __shared__ float red[HH][33];
    __shared__ float fin[HH];

    const int b = blockIdx.x;
    const int tid = threadIdx.x;
    const int warp = tid >> 5;
    const int lane = tid & 31;
    const int gid = lane >> 2;
    const int tg = lane & 3;

    // build q B-frag tables (hi/lo), folding the partial reduce + bias + scale
    {
        const int ks = tid >> 5, L = tid & 31;
        const int h = L >> 2, e0 = h * DD + ks * 16 + (L & 3) * 2;
        const float* pp = g_part + (size_t)b * EE + e0;
        float2 a0 = *(const float2*)(pp);
        float2 b0 = *(const float2*)(pp + 1 * BB * EE);
        float2 c0 = *(const float2*)(pp + 2 * BB * EE);
        float2 d0 = *(const float2*)(pp + 3 * BB * EE);
        float2 bi0 = *(const float2*)(b_in + e0);
        float2 a1 = *(const float2*)(pp + 8);
        float2 b1 = *(const float2*)(pp + 1 * BB * EE + 8);
        float2 c1 = *(const float2*)(pp + 2 * BB * EE + 8);
        float2 d1 = *(const float2*)(pp + 3 * BB * EE + 8);
        float2 bi1 = *(const float2*)(b_in + e0 + 8);
        float2 v0 = make_float2((a0.x + b0.x + c0.x + d0.x + bi0.x) * QSCALE,
                                (a0.y + b0.y + c0.y + d0.y + bi0.y) * QSCALE);
        float2 v1 = make_float2((a1.x + b1.x + c1.x + d1.x + bi1.x) * QSCALE,
                                (a1.y + b1.y + c1.y + d1.y + bi1.y) * QSCALE);
        uint32_t h0 = bfhi(v0), l0 = bflo(v0, h0);
        uint32_t h1 = bfhi(v1), l1 = bflo(v1, h1);
        qbA[tid] = make_uint2(h0, h1);
        qbB[tid] = make_uint2(l0, l1);
    }
    __syncthreads();

    // ---- scores via mma: warp handles 4 m-tiles of 16 s ----
    const float* Kb = key + (size_t)b * SS * DD;
    const int*   Mb = mask + (size_t)b * SS;

    for (int i = 0; i < 4; i++) {
        const int mt = warp * 4 + i;
        const int s0 = mt * 16 + gid;
        const float* K0 = Kb + (size_t)s0 * DD + tg * 2;
        float c[4] = {0.0f, 0.0f, 0.0f, 0.0f};
        #pragma unroll 4
        for (int ks = 0; ks < 32; ks++) {
            const float* kp = K0 + ks * 16;
            float2 va0 = *(const float2*)(kp);
            float2 va1 = *(const float2*)(kp + 8 * DD);
            float2 va2 = *(const float2*)(kp + 8);
            float2 va3 = *(const float2*)(kp + 8 * DD + 8);
            uint32_t ah[4], al[4];
            ah[0] = bfhi(va0); al[0] = bflo(va0, ah[0]);
            ah[1] = bfhi(va1); al[1] = bflo(va1, ah[1]);
            ah[2] = bfhi(va2); al[2] = bflo(va2, ah[2]);
            ah[3] = bfhi(va3); al[3] = bflo(va3, ah[3]);
            uint2 bh = qbA[ks * 32 + lane];
            uint2 bl = qbB[ks * 32 + lane];
            mma16816(c, ah, (const uint32_t*)&bh);
            mma16816(c, al, (const uint32_t*)&bh);
            mma16816(c, ah, (const uint32_t*)&bl);
        }
        const int s1 = s0 + 8, h0 = tg * 2;
        const int m0 = Mb[s0], m1 = Mb[s1];
        sc[s0 * 8 + h0]     = m0 ? c[0] : -1e9f;
        sc[s0 * 8 + h0 + 1] = m0 ? c[1] : -1e9f;
        sc[s1 * 8 + h0]     = m1 ? c[2] : -1e9f;
        sc[s1 * 8 + h0 + 1] = m1 ? c[3] : -1e9f;
    }
    __syncthreads();

    // ---- softmax: thread owns 2 contiguous s-rows (16 floats) ----
    {
        const int base = tid * 16;
        float4 r[4];
        #pragma unroll
        for (int i = 0; i < 4; i++) r[i] = *(float4*)(sc + base + i * 4);

        float m[HH];
        m[0] = fmaxf(r[0].x, r[2].x); m[1] = fmaxf(r[0].y, r[2].y);
        m[2] = fmaxf(r[0].z, r[2].z); m[3] = fmaxf(r[0].w, r[2].w);
        m[4] = fmaxf(r[1].x, r[3].x); m[5] = fmaxf(r[1].y, r[3].y);
        m[6] = fmaxf(r[1].z, r[3].z); m[7] = fmaxf(r[1].w, r[3].w);
        #pragma unroll
        for (int off = 16; off; off >>= 1)
            #pragma unroll
            for (int h = 0; h < HH; h++)
                m[h] = fmaxf(m[h], __shfl_xor_sync(0xffffffffu, m[h], off));
        if (lane < HH) red[lane][warp] = m[lane];
        __syncthreads();
        if (warp < HH) {
            float v = red[warp][lane];
            #pragma unroll
            for (int off = 16; off; off >>= 1)
                v = fmaxf(v, __shfl_xor_sync(0xffffffffu, v, off));
            if (lane == 0) fin[warp] = v;
        }
        __syncthreads();
        #pragma unroll
        for (int h = 0; h < HH; h++) m[h] = fin[h];
        __syncthreads();

        float s[HH];
        #pragma unroll
        for (int h = 0; h < HH; h++) s[h] = 0.0f;
        #pragma unroll
        for (int i = 0; i < 4; i++) {
            const int hb = (i & 1) * 4;
            r[i].x = __expf(r[i].x - m[hb + 0]); s[hb + 0] += r[i].x;
            r[i].y = __expf(r[i].y - m[hb + 1]); s[hb + 1] += r[i].y;
            r[i].z = __expf(r[i].z - m[hb + 2]); s[hb + 2] += r[i].z;
            r[i].w = __expf(r[i].w - m[hb + 3]); s[hb + 3] += r[i].w;
        }
        #pragma unroll
        for (int off = 16; off; off >>= 1)
            #pragma unroll
            for (int h = 0; h < HH; h++)
                s[h] += __shfl_xor_sync(0xffffffffu, s[h], off);
        if (lane < HH) red[lane][warp] = s[lane];
        __syncthreads();
        if (warp < HH) {
            float v = red[warp][lane];
            #pragma unroll
            for (int off = 16; off; off >>= 1)
                v += __shfl_xor_sync(0xffffffffu, v, off);
            if (lane == 0) fin[warp] = 1.0f / v;
        }
        __syncthreads();
        #pragma unroll
        for (int h = 0; h < HH; h++) s[h] = fin[h];

        #pragma unroll
        for (int i = 0; i < 4; i++) {
            const int hb = (i & 1) * 4;
            r[i].x *= s[hb + 0];
            r[i].y *= s[hb + 1];
            r[i].z *= s[hb + 2];
            r[i].w *= s[hb + 3];
            *(float4*)(sc + base + i * 4) = r[i];
        }
    }
    __syncthreads();

    // ---- pass 2: thread owns (d-quad, head-quad, s-quarter) ----
    const int d4 = (tid & 127) * 4;
    const int h0 = ((tid >> 7) & 1) * 4;
    const int sg = tid >> 8;             // 0..3
    const float* Vb = value + (size_t)b * SS * DD;

    float4 a0 = {0,0,0,0}, a1 = a0, a2 = a0, a3 = a0;
    const int s_beg = sg * 512;
    #pragma unroll 2
    for (int s = s_beg; s < s_beg + 512; s += 2) {
        float4 v0 = *(const float4*)(Vb + (size_t)s * DD + d4);
        float4 v1 = *(const float4*)(Vb + (size_t)(s + 1) * DD + d4);
        float4 p0 = *(const float4*)(sc + s * 8 + h0);
        float4 p1 = *(const float4*)(sc + (s + 1) * 8 + h0);
        fma4(a0, p0.x, v0); fma4(a1, p0.y, v0); fma4(a2, p0.z, v0); fma4(a3, p0.w, v0);
        fma4(a0, p1.x, v1); fma4(a1, p1.y, v1); fma4(a2, p1.z, v1); fma4(a3, p1.w, v1);
    }
    __syncthreads();  // everyone done reading sc (reuse as 4 partial buffers)

    {
        float* dst = sc + sg * 4096;
        *(float4*)(dst + (h0 + 0) * DD + d4) = a0;
        *(float4*)(dst + (h0 + 1) * DD + d4) = a1;
        *(float4*)(dst + (h0 + 2) * DD + d4) = a2;
        *(float4*)(dst + (h0 + 3) * DD + d4) = a3;
    }
    __syncthreads();

    const int idx = tid * 4;
    float4 r0 = *(float4*)(sc + idx);
    float4 r1 = *(float4*)(sc + 4096 + idx);
    float4 r2 = *(float4*)(sc + 8192 + idx);
    float4 r3 = *(float4*)(sc + 12288 + idx);
    float4 r;
    r.x = r0.x + r1.x + r2.x + r3.x;
    r.y = r0.y + r1.y + r2.y + r3.y;
    r.z = r0.z + r1.z + r2.z + r3.z;
    r.w = r0.w + r1.w + r2.w + r3.w;
    *(float4*)(g_x + (size_t)b * EE + idx) = r;
}

// ---------------------------------------------------------------------------
extern "C" void kernel_launch(void* const* d_in, const int* in_sizes, int n_in,
                              void* d_out, int out_size) {
    const float* query = (const float*)d_in[0];
    const float* key   = (const float*)d_in[1];
    const float* value = (const float*)d_in[2];
    const int*   mask  = (const int*)d_in[3];
    const float* W_in  = (const float*)d_in[4];
    const float* b_in  = (const float*)d_in[5];
    const float* W_out = (const float*)d_in[6];
    const float* b_out = (const float*)d_in[7];
    float* out = (float*)d_out;

    const int smem_attn = 81920;  // sc 64K + qbA 8K + qbB 8K
    cudaFuncSetAttribute(attn_kernel, cudaFuncAttributeMaxDynamicSharedMemorySize, smem_attn);
    cudaFuncSetAttribute(gemm_part<512, 128>,   cudaFuncAttributeMaxDynamicSharedMemorySize, GEMM_SMEM);
    cudaFuncSetAttribute(gemm_part<4096, 1024>, cudaFuncAttributeMaxDynamicSharedMemorySize, GEMM_SMEM);

    float* gx; cudaGetSymbolAddress((void**)&gx, g_x);
    float* gp; cudaGetSymbolAddress((void**)&gp, g_part);

    dim3 ggrid(EE / 64, KSPLIT);   // 256 CTAs

    gemm_part<512, 128><<<ggrid, 256, GEMM_SMEM>>>(query, W_in, gp);
    attn_kernel<<<BB, 1024, smem_attn>>>(key, value, mask, b_in);
    gemm_part<4096, 1024><<<ggrid, 256, GEMM_SMEM>>>(gx, W_out, gp);
    reduce_part<<<BB * EE / 1024, 256>>>(b_out, out, 1.0f);
}